// round 15
// baseline (speedup 1.0000x reference)
#include <cuda_runtime.h>
#include <cuda_bf16.h>
#include <math.h>

#define TN     256
#define DDIM   6
#define NEXP   540
#define NGEO   20
#define KPHI   27
#define NPROB  560          // 540 experts + 20 baselines
#define NTEST  1024
#define PACK   32896        // 256*257/2
#define JIT    1e-4f

// ---------------- packed f32x2 helpers (sm_103a FFMA2) ----------------
__device__ __forceinline__ unsigned long long pk2(float lo, float hi) {
    unsigned long long r;
    asm("mov.b64 %0, {%1, %2};" : "=l"(r) : "f"(lo), "f"(hi));
    return r;
}
__device__ __forceinline__ unsigned long long fma2(unsigned long long a,
                                                   unsigned long long b,
                                                   unsigned long long c) {
    unsigned long long r;
    asm("fma.rn.f32x2 %0, %1, %2, %3;" : "=l"(r) : "l"(a), "l"(b), "l"(c));
    return r;
}
__device__ __forceinline__ float2 upk2(unsigned long long a) {
    float lo, hi;
    asm("mov.b64 {%0, %1}, %2;" : "=f"(lo), "=f"(hi) : "l"(a));
    return make_float2(lo, hi);
}

// ---------------- static device scratch ----------------
__device__ float g_L[(size_t)NPROB * PACK];           // packed column-major lower L
__device__ float g_w[NPROB * TN];                     // w = L^-1 y
__device__ float g_dinv[(size_t)NPROB * 8 * 32 * 32]; // 32x32 diag-block inverses [tile][s][r]
__device__ int   g_used[NPROB];
__device__ int   g_route_e[NTEST];
__device__ int   g_route_g[NTEST];
__device__ float g_mu_e[NTEST],  g_var_e[NTEST],  g_prior_e[NTEST];
__device__ float g_mu_b[NTEST],  g_var_b[NTEST],  g_prior_b[NTEST];

__device__ __forceinline__ int cpidx(int j) { return j * TN - ((j * (j - 1)) >> 1); }

// ---------------- kernel 0: clear used flags ----------------
__global__ void k_zero() {
    int i = blockIdx.x * blockDim.x + threadIdx.x;
    if (i < NPROB) g_used[i] = 0;
}

// ---------------- kernel 1: 2-level GMM routing ----------------
__global__ void k_route(const float* __restrict__ Xt,
                        const float* __restrict__ smean, const float* __restrict__ sscale,
                        const float* __restrict__ gm,    const float* __restrict__ glv,
                        const float* __restrict__ glw,
                        const float* __restrict__ pm,    const float* __restrict__ plv,
                        const float* __restrict__ plw,
                        const int*   __restrict__ nmask)
{
    int n = blockIdx.x * blockDim.x + threadIdx.x;
    if (n >= NTEST) return;
    float xs[DDIM];
#pragma unroll
    for (int d = 0; d < DDIM; ++d) xs[d] = (Xt[n * DDIM + d] - smean[d]) / sscale[d];

    float best = -3e38f; int gb = 0;
    for (int gi = 0; gi < NGEO; ++gi) {
        float acc = 0.f;
#pragma unroll
        for (int d = 0; d < DDIM; ++d) {
            float lv = glv[gi * DDIM + d];
            float t  = xs[d] - gm[gi * DDIM + d];
            acc += lv + t * t * expf(-lv);
        }
        float lp = glw[gi] - 0.5f * acc;
        if (lp > best) { best = lp; gb = gi; }
    }
    float bestp = -3e38f; int kb = 0;
    for (int kk = 0; kk < KPHI; ++kk) {
        int base = (gb * KPHI + kk) * DDIM;
        float acc = 0.f;
#pragma unroll
        for (int d = 0; d < DDIM; ++d) {
            float lv = plv[base + d];
            float t  = xs[d] - pm[base + d];
            acc += lv + t * t * expf(-lv);
        }
        float lp = plw[gb * KPHI + kk] - 0.5f * acc;
        if (lp > bestp) { bestp = lp; kb = kk; }
    }
    int e = gb * KPHI + kb;
    g_route_e[n] = e;
    g_route_g[n] = gb;
    if (nmask[e] != 0) g_used[e] = 1;
    g_used[NEXP + gb] = 1;
}

// ---------------- kernel 2: build K, blocked Cholesky, Dinv, w-solve, export ----------------
// R14 + rsqrtf in the 8x8 diag factor (isolated change).
// smem (floats): sA[PACK] | sXp[256*8] | sPan[256*8] | sW[256] | sDinv[8192]
#define SMEM_FLOATS (PACK + TN*8 + TN*8 + TN + 8192)

__global__ void __launch_bounds__(512, 1) k_factor(
    const float* __restrict__ X_exp,  const float* __restrict__ Y_exp,
    const float* __restrict__ X_base, const float* __restrict__ Y_base,
    const float* __restrict__ lls_e, const float* __restrict__ los_e, const float* __restrict__ lno_e,
    const float* __restrict__ lls_b, const float* __restrict__ los_b, const float* __restrict__ lno_b)
{
    int b = blockIdx.x;
    if (!g_used[b]) return;

    extern __shared__ float sm[];
    float* sA    = sm;
    float* sXp   = sA + PACK;
    float* sPan  = sXp + TN * 8;
    float* sW    = sPan + TN * 8;
    float* sDinv = sW + TN;

    int tid  = threadIdx.x;
    int wid  = tid >> 5;
    int lane = tid & 31;

    const float* Xs; const float* Ys; float lls, los, lno;
    if (b < NEXP) {
        Xs = X_exp + (size_t)b * TN * DDIM;  Ys = Y_exp + b * TN;
        lls = lls_e[b]; los = los_e[b]; lno = lno_e[b];
    } else {
        int gb = b - NEXP;
        Xs = X_base + (size_t)gb * TN * DDIM; Ys = Y_base + gb * TN;
        lls = lls_b[gb]; los = los_b[gb]; lno = lno_b[gb];
    }
    float ls2 = expf(2.f * lls);
    float osv = expf(los);
    float nv  = expf(lno) + JIT;
    float c0  = -0.5f / ls2;

    if (tid < TN) {
        int i = tid;
        float v[8];
#pragma unroll
        for (int d = 0; d < DDIM; ++d) v[d] = Xs[i * DDIM + d];
        v[6] = 0.f; v[7] = 0.f;
        float4* dst = (float4*)&sXp[i * 8];
        dst[0] = make_float4(v[0], v[1], v[2], v[3]);
        dst[1] = make_float4(v[4], v[5], v[6], v[7]);
        sW[i] = Ys[i];
    }
    __syncthreads();

    // ---- build K ----
    {
        int row  = tid & 255;
        int half = tid >> 8;
        const float4* X4 = (const float4*)sXp;
        float4 xi0 = X4[row * 2], xi1 = X4[row * 2 + 1];
        int jmid = (row + 1) >> 1;
        int jlo = half ? jmid : 0;
        int jhi = half ? (row + 1) : jmid;
        int idx = cpidx(jlo) + row - jlo;
        for (int j = jlo; j < jhi; ++j) {
            float4 xj0 = X4[j * 2], xj1 = X4[j * 2 + 1];
            float t0 = xi0.x - xj0.x, t1 = xi0.y - xj0.y, t2 = xi0.z - xj0.z, t3 = xi0.w - xj0.w;
            float t4 = xi1.x - xj1.x, t5 = xi1.y - xj1.y;
            float d2 = t0*t0 + t1*t1 + t2*t2 + t3*t3 + t4*t4 + t5*t5;
            float kv = (j == row) ? (osv + nv) : (osv * __expf(c0 * d2));
            sA[idx] = kv;
            idx += 255 - j;
        }
    }
    __syncthreads();

    const float4* pan4 = (const float4*)sPan;

    // ---- blocked Cholesky, panel width 8 ----
    for (int q = 0; q < 32; ++q) {
        int j0   = q * 8;
        int base = j0 + 8;
        int R    = TN - base;

        if (tid < TN) {
            float Ld[8][8];
            float dinv[8];
#pragma unroll
            for (int c = 0; c < 8; ++c) {
                int bidx = cpidx(j0 + c);
#pragma unroll
                for (int r = 0; r < 8; ++r)
                    if (r >= c) Ld[r][c] = sA[bidx + (r - c)];
            }
#pragma unroll
            for (int c = 0; c < 8; ++c) {
                float dsq = Ld[c][c];
#pragma unroll
                for (int p = 0; p < 8; ++p) if (p < c) dsq -= Ld[c][p] * Ld[c][p];
                float inv = rsqrtf(dsq);       // kills sqrt+div serial chain (validated in R9)
                float dl  = dsq * inv;
                Ld[c][c] = dl;
                dinv[c] = inv;
#pragma unroll
                for (int r = 0; r < 8; ++r) {
                    if (r > c) {
                        float v = Ld[r][c];
#pragma unroll
                        for (int p = 0; p < 8; ++p) if (p < c) v -= Ld[r][p] * Ld[c][p];
                        Ld[r][c] = v * inv;
                    }
                }
            }
            if (tid < R) {
                int i = base + tid;
                float a[8];
#pragma unroll
                for (int c = 0; c < 8; ++c) a[c] = sA[cpidx(j0 + c) + (i - (j0 + c))];
#pragma unroll
                for (int c = 0; c < 8; ++c) {
                    float v = a[c];
#pragma unroll
                    for (int p = 0; p < 8; ++p) if (p < c) v -= a[p] * Ld[c][p];
                    a[c] = v * dinv[c];
                }
#pragma unroll
                for (int c = 0; c < 8; ++c) sA[cpidx(j0 + c) + (i - (j0 + c))] = a[c];
                float4* sp = (float4*)&sPan[tid * 8];
                sp[0] = make_float4(a[0], a[1], a[2], a[3]);
                sp[1] = make_float4(a[4], a[5], a[6], a[7]);
            }
#pragma unroll
            for (int r = 0; r < 8; ++r) {
                if (tid == r) {
#pragma unroll
                    for (int c = 0; c < 8; ++c)
                        if (c <= r) sA[cpidx(j0 + c) + (r - c)] = Ld[r][c];
                }
            }
        }
        __syncthreads();

        // ---- SYRK: warp per 8-row tile; packed f32x2 FMA inner dot ----
        if (R > 0) {
            int nt = (R + 7) >> 3;
            for (int rt = wid; rt < nt; rt += 16) {
                int r0 = rt << 3;
                unsigned long long pn[8][4];   // negated packed panel rows
#pragma unroll
                for (int rr = 0; rr < 8; ++rr) {
                    if (r0 + rr < R) {
                        float4 pi0 = pan4[(r0 + rr) * 2];
                        float4 pi1 = pan4[(r0 + rr) * 2 + 1];
                        pn[rr][0] = pk2(-pi0.x, -pi0.y);
                        pn[rr][1] = pk2(-pi0.z, -pi0.w);
                        pn[rr][2] = pk2(-pi1.x, -pi1.y);
                        pn[rr][3] = pk2(-pi1.z, -pi1.w);
                    } else {
                        pn[rr][0] = 0ull; pn[rr][1] = 0ull;
                        pn[rr][2] = 0ull; pn[rr][3] = 0ull;
                    }
                }
                int rmax = min(r0 + 7, R - 1);
                for (int kb = 0; kb <= rmax; kb += 32) {
                    int kk = kb + lane;
                    float4 q0 = make_float4(0.f, 0.f, 0.f, 0.f);
                    float4 q1 = q0;
                    if (kk <= rmax) {
                        q0 = pan4[kk * 2];
                        q1 = pan4[kk * 2 + 1];
                    }
                    unsigned long long qp0 = pk2(q0.x, q0.y);
                    unsigned long long qp1 = pk2(q0.z, q0.w);
                    unsigned long long qp2 = pk2(q1.x, q1.y);
                    unsigned long long qp3 = pk2(q1.z, q1.w);
                    int c = base + kk;
                    int cbase = c * TN - ((c * (c - 1)) >> 1);
#pragma unroll
                    for (int rr = 0; rr < 8; ++rr) {
                        int rho = r0 + rr;
                        if (kk <= rho && rho < R) {
                            int idx = cbase + (rho - kk);
                            float v = sA[idx];
                            unsigned long long t = fma2(pn[rr][0], qp0, pk2(v, 0.f));
                            t = fma2(pn[rr][1], qp1, t);
                            t = fma2(pn[rr][2], qp2, t);
                            t = fma2(pn[rr][3], qp3, t);
                            float2 s = upk2(t);
                            sA[idx] = s.x + s.y;
                        }
                    }
                }
            }
        }
        __syncthreads();
    }

    if (tid < TN) sXp[tid] = 1.0f / sA[cpidx(tid)];
    __syncthreads();

    // ---- epilogue phase 1: warps 1-8 Dinv (smem + global) | warps 9-15 export L ----
    if (wid >= 1 && wid <= 8) {
        int t = wid - 1;
        int s = lane;
        int c0t = 32 * t;
        float x[32];
#pragma unroll
        for (int r = 0; r < 32; ++r) {
            float sum = 0.f;
#pragma unroll
            for (int k = 0; k < 32; ++k) {
                if (k < r) sum += sA[cpidx(c0t + k) + (r - k)] * x[k];
            }
            float ivr = sXp[c0t + r];
            x[r] = (r == s) ? ivr : -sum * ivr;
        }
        float* dsts = sDinv + t * 1024 + s * 32;
        float* dstg = g_dinv + (size_t)b * 8192 + t * 1024 + s * 32;
#pragma unroll
        for (int r = 0; r < 32; ++r) { dsts[r] = x[r]; dstg[r] = x[r]; }
    } else if (wid >= 9) {
        const float4* s4 = (const float4*)sA;
        float4* d4 = (float4*)(g_L + (size_t)b * PACK);
        for (int i = tid - 288; i < PACK / 4; i += 224) d4[i] = s4[i];
    }
    __syncthreads();

    // ---- epilogue phase 2: parallel 8-step w-solve (threads 0-255, row-per-thread) ----
    {
        int r  = tid & 255;
        int hw = r >> 5;
        float acc = (tid < 256) ? sW[r] : 0.f;
#pragma unroll
        for (int T = 0; T < 8; ++T) {
            if (tid < 256 && hw == T) {
                const float* Dt = sDinv + T * 1024;
                float v0 = 0.f, v1 = 0.f, v2 = 0.f, v3 = 0.f;
#pragma unroll
                for (int s = 0; s < 32; s += 4) {
                    float d0 = Dt[(s+0) * 32 + lane];
                    float d1 = Dt[(s+1) * 32 + lane];
                    float d2 = Dt[(s+2) * 32 + lane];
                    float d3 = Dt[(s+3) * 32 + lane];
                    float b0 = __shfl_sync(0xffffffffu, acc, s+0);
                    float b1 = __shfl_sync(0xffffffffu, acc, s+1);
                    float b2 = __shfl_sync(0xffffffffu, acc, s+2);
                    float b3 = __shfl_sync(0xffffffffu, acc, s+3);
                    v0 += d0 * b0; v1 += d1 * b1; v2 += d2 * b2; v3 += d3 * b3;
                }
                sW[r] = (v0 + v1) + (v2 + v3);
            }
            __syncthreads();
            if (tid < 256 && T < 7 && hw > T) {
                int c0i = 32 * T;
                int idx = cpidx(c0i) + (r - c0i);
                float a0 = 0.f, a1 = 0.f, a2 = 0.f, a3 = 0.f;
#pragma unroll
                for (int j = 0; j < 8; ++j) {
                    int c = c0i + j * 4;
                    float z0 = sW[c], z1 = sW[c+1], z2 = sW[c+2], z3 = sW[c+3];
                    float l0 = sA[idx]; idx += 255 - c;
                    float l1 = sA[idx]; idx += 254 - c;
                    float l2 = sA[idx]; idx += 253 - c;
                    float l3 = sA[idx]; idx += 252 - c;
                    a0 += l0 * z0; a1 += l1 * z1; a2 += l2 * z2; a3 += l3 * z3;
                }
                acc -= (a0 + a1) + (a2 + a3);
            }
        }
        if (tid < 256) g_w[b * TN + r] = sW[r];
    }
}

// ---------------- kernel 3: prediction, block-per-task, row-per-thread ----------------
// (byte-identical to R13/R14 — proven best)
__global__ void __launch_bounds__(256) k_predict(
    const float* __restrict__ Xt,
    const float* __restrict__ X_exp, const float* __restrict__ X_base,
    const float* __restrict__ lls_e, const float* __restrict__ los_e, const float* __restrict__ lno_e,
    const float* __restrict__ lls_b, const float* __restrict__ los_b, const float* __restrict__ lno_b,
    const int*   __restrict__ nmask)
{
    __shared__ float sDv[8192];
    __shared__ float sZ[TN];
    __shared__ float sRed[16];

    int task = blockIdx.x;            // 0..2047
    int n = task >> 1;
    bool is_base = (task & 1);

    int p; const float* Xtr; float lls, los, lno;
    if (!is_base) {
        int e = g_route_e[n];
        if (nmask[e] == 0) return;    // uniform across block
        p = e; Xtr = X_exp + (size_t)e * TN * DDIM;
        lls = lls_e[e]; los = los_e[e]; lno = lno_e[e];
    } else {
        int g = g_route_g[n];
        p = NEXP + g; Xtr = X_base + (size_t)g * TN * DDIM;
        lls = lls_b[g]; los = los_b[g]; lno = lno_b[g];
    }
    float ls2 = expf(2.f * lls);
    float osv = expf(los);
    float nv  = expf(lno) + JIT;
    float c0  = -0.5f / ls2;

    int r    = threadIdx.x;           // row 0..255
    int wid  = r >> 5;
    int lane = r & 31;

    // stage Dinv into smem (coalesced float4)
    {
        const float4* dv4 = (const float4*)(g_dinv + (size_t)p * 8192);
        float4* dd4 = (float4*)sDv;
#pragma unroll
        for (int i = 0; i < 8; ++i) dd4[r + i * 256] = dv4[r + i * 256];
    }

    // k*(x_n, Xtr[r]) -> initial residual acc
    float acc;
    {
        float d2 = 0.f;
#pragma unroll
        for (int d = 0; d < DDIM; ++d) {
            float tv = Xt[n * DDIM + d] - Xtr[r * DDIM + d];
            d2 += tv * tv;
        }
        acc = osv * __expf(c0 * d2);
    }
    float wr = g_w[p * TN + r];
    const float* Lp = g_L + (size_t)p * PACK;
    __syncthreads();   // sDv ready

    // right-looking block forward solve: 8 steps
#pragma unroll
    for (int T = 0; T < 8; ++T) {
        int c0i = 32 * T;
        int idx0 = c0i * TN - ((c0i * (c0i - 1)) >> 1) + (r - c0i);
        float lv[16];
        // prefetch first 16 L values BEFORE the barrier (addresses data-independent)
        if (T < 7 && wid > T) {
            int idx = idx0;
#pragma unroll
            for (int k = 0; k < 16; ++k) { lv[k] = Lp[idx]; idx += 255 - (c0i + k); }
        }
        if (wid == T) {
            // z_tile = Dinv_T * acc_tile (smem Dinv, shfl broadcast)
            const float* Dt = sDv + T * 1024;
            float v0 = 0.f, v1 = 0.f, v2 = 0.f, v3 = 0.f;
#pragma unroll
            for (int s = 0; s < 32; s += 4) {
                float d0 = Dt[(s+0) * 32 + lane];
                float d1 = Dt[(s+1) * 32 + lane];
                float d2 = Dt[(s+2) * 32 + lane];
                float d3 = Dt[(s+3) * 32 + lane];
                float b0 = __shfl_sync(0xffffffffu, acc, s+0);
                float b1 = __shfl_sync(0xffffffffu, acc, s+1);
                float b2 = __shfl_sync(0xffffffffu, acc, s+2);
                float b3 = __shfl_sync(0xffffffffu, acc, s+3);
                v0 += d0 * b0; v1 += d1 * b1; v2 += d2 * b2; v3 += d3 * b3;
            }
            sZ[r] = (v0 + v1) + (v2 + v3);
        }
        __syncthreads();
        if (T < 7 && wid > T) {
            float a0 = 0.f, a1 = 0.f, a2 = 0.f, a3 = 0.f;
            // first 16 from prefetched registers
#pragma unroll
            for (int k = 0; k < 16; k += 4) {
                a0 += lv[k+0] * sZ[c0i+k+0];
                a1 += lv[k+1] * sZ[c0i+k+1];
                a2 += lv[k+2] * sZ[c0i+k+2];
                a3 += lv[k+3] * sZ[c0i+k+3];
            }
            // remaining 16 streamed (independent loads)
            int idx = idx0 + 16 * 255 - 16 * c0i - 120;
#pragma unroll
            for (int j = 4; j < 8; ++j) {
                int c = c0i + j * 4;
                float z0 = sZ[c], z1 = sZ[c+1], z2 = sZ[c+2], z3 = sZ[c+3];
                float l0 = Lp[idx]; idx += 255 - c;
                float l1 = Lp[idx]; idx += 254 - c;
                float l2 = Lp[idx]; idx += 253 - c;
                float l3 = Lp[idx]; idx += 252 - c;
                a0 += l0 * z0; a1 += l1 * z1; a2 += l2 * z2; a3 += l3 * z3;
            }
            acc -= (a0 + a1) + (a2 + a3);
        }
    }

    // reduce qq = |z|^2, mu = z.w
    float z = sZ[r];
    float qq = z * z;
    float mu = z * wr;
#pragma unroll
    for (int o = 16; o; o >>= 1) {
        qq += __shfl_xor_sync(0xffffffffu, qq, o);
        mu += __shfl_xor_sync(0xffffffffu, mu, o);
    }
    if (lane == 0) { sRed[wid] = qq; sRed[8 + wid] = mu; }
    __syncthreads();
    if (r == 0) {
        float tq = 0.f, tm = 0.f;
#pragma unroll
        for (int i = 0; i < 8; ++i) { tq += sRed[i]; tm += sRed[8 + i]; }
        float var = fmaxf(osv - tq, JIT) + nv;
        float prior = osv + nv;
        if (!is_base) { g_mu_e[n] = tm; g_var_e[n] = var; g_prior_e[n] = prior; }
        else          { g_mu_b[n] = tm; g_var_b[n] = var; g_prior_b[n] = prior; }
    }
}

// ---------------- kernel 4: rBCM combine ----------------
__global__ void k_combine(const int* __restrict__ nmask, float* __restrict__ out)
{
    int n = blockIdx.x * blockDim.x + threadIdx.x;
    if (n >= NTEST) return;
    int e = g_route_e[n];
    bool isnull = (nmask[e] == 0);
    float mub = g_mu_b[n], varb = g_var_b[n], prb = g_prior_b[n];
    float bb = fmaxf(0.5f * (logf(prb) - logf(varb)), 0.f);
    float be = 0.f, te = 0.f, me = 0.f;
    if (!isnull) {
        float mue = g_mu_e[n], vare = g_var_e[n], pre = g_prior_e[n];
        be = fmaxf(0.5f * (logf(pre) - logf(vare)), 0.f);
        te = be / vare;
        me = be * mue / vare;
    }
    float prec = te + bb / varb + (1.f - be - bb) / prb;
    prec = fmaxf(prec, 1e-6f);
    float mean = (me + bb * mub / varb) / prec;
    out[n] = mean;
    out[NTEST + n] = 1.f / prec;
}

// ---------------- launch ----------------
extern "C" void kernel_launch(void* const* d_in, const int* in_sizes, int n_in,
                              void* d_out, int out_size)
{
    const float* X_test   = (const float*)d_in[0];
    const float* X_exp    = (const float*)d_in[1];
    const float* Y_exp    = (const float*)d_in[2];
    const float* X_base   = (const float*)d_in[3];
    const float* Y_base   = (const float*)d_in[4];
    const float* lls_e    = (const float*)d_in[5];
    const float* los_e    = (const float*)d_in[6];
    const float* lno_e    = (const float*)d_in[7];
    const float* lls_b    = (const float*)d_in[8];
    const float* los_b    = (const float*)d_in[9];
    const float* lno_b    = (const float*)d_in[10];
    const float* smean    = (const float*)d_in[11];
    const float* sscale   = (const float*)d_in[12];
    const float* gm       = (const float*)d_in[13];
    const float* glv      = (const float*)d_in[14];
    const float* glw      = (const float*)d_in[15];
    const float* pm       = (const float*)d_in[16];
    const float* plv      = (const float*)d_in[17];
    const float* plw      = (const float*)d_in[18];
    const int*   nmask    = (const int*)d_in[19];
    float* out = (float*)d_out;

    static_assert(SMEM_FLOATS * 4 <= 232448, "smem factor");
    cudaFuncSetAttribute(k_factor, cudaFuncAttributeMaxDynamicSharedMemorySize,
                         SMEM_FLOATS * 4);

    k_zero<<<(NPROB + 255) / 256, 256>>>();
    k_route<<<(NTEST + 255) / 256, 256>>>(X_test, smean, sscale, gm, glv, glw,
                                          pm, plv, plw, nmask);
    k_factor<<<NPROB, 512, SMEM_FLOATS * 4>>>(X_exp, Y_exp, X_base, Y_base,
                                              lls_e, los_e, lno_e,
                                              lls_b, los_b, lno_b);
    k_predict<<<2 * NTEST, 256>>>(X_test, X_exp, X_base,
                                  lls_e, los_e, lno_e,
                                  lls_b, los_b, lno_b, nmask);
    k_combine<<<(NTEST + 255) / 256, 256>>>(nmask, out);
}

// round 16
// speedup vs baseline: 1.4454x; 1.4454x over previous
#include <cuda_runtime.h>
#include <cuda_bf16.h>
#include <math.h>

#define TN     256
#define DDIM   6
#define NEXP   540
#define NGEO   20
#define KPHI   27
#define NPROB  560          // 540 experts + 20 baselines
#define NTEST  1024
#define PACK   32896        // 256*257/2
#define JIT    1e-4f

// ---------------- packed f32x2 helpers (sm_103a FFMA2) ----------------
__device__ __forceinline__ unsigned long long pk2(float lo, float hi) {
    unsigned long long r;
    asm("mov.b64 %0, {%1, %2};" : "=l"(r) : "f"(lo), "f"(hi));
    return r;
}
__device__ __forceinline__ unsigned long long fma2(unsigned long long a,
                                                   unsigned long long b,
                                                   unsigned long long c) {
    unsigned long long r;
    asm("fma.rn.f32x2 %0, %1, %2, %3;" : "=l"(r) : "l"(a), "l"(b), "l"(c));
    return r;
}
__device__ __forceinline__ float2 upk2(unsigned long long a) {
    float lo, hi;
    asm("mov.b64 {%0, %1}, %2;" : "=f"(lo), "=f"(hi) : "l"(a));
    return make_float2(lo, hi);
}

// ---------------- static device scratch ----------------
__device__ float g_L[(size_t)NPROB * PACK];           // packed column-major lower L
__device__ float g_w[NPROB * TN];                     // w = L^-1 y
__device__ float g_dinv[(size_t)NPROB * 8 * 32 * 32]; // 32x32 diag-block inverses [tile][s][r]
__device__ int   g_used[NPROB];
__device__ int   g_route_e[NTEST];
__device__ int   g_route_g[NTEST];
__device__ float g_mu_e[NTEST],  g_var_e[NTEST],  g_prior_e[NTEST];
__device__ float g_mu_b[NTEST],  g_var_b[NTEST],  g_prior_b[NTEST];

__device__ __forceinline__ int cpidx(int j) { return j * TN - ((j * (j - 1)) >> 1); }

// ---------------- kernel 0: clear used flags ----------------
__global__ void k_zero() {
    int i = blockIdx.x * blockDim.x + threadIdx.x;
    if (i < NPROB) g_used[i] = 0;
}

// ---------------- kernel 1: 2-level GMM routing ----------------
__global__ void k_route(const float* __restrict__ Xt,
                        const float* __restrict__ smean, const float* __restrict__ sscale,
                        const float* __restrict__ gm,    const float* __restrict__ glv,
                        const float* __restrict__ glw,
                        const float* __restrict__ pm,    const float* __restrict__ plv,
                        const float* __restrict__ plw,
                        const int*   __restrict__ nmask)
{
    int n = blockIdx.x * blockDim.x + threadIdx.x;
    if (n >= NTEST) return;
    float xs[DDIM];
#pragma unroll
    for (int d = 0; d < DDIM; ++d) xs[d] = (Xt[n * DDIM + d] - smean[d]) / sscale[d];

    float best = -3e38f; int gb = 0;
    for (int gi = 0; gi < NGEO; ++gi) {
        float acc = 0.f;
#pragma unroll
        for (int d = 0; d < DDIM; ++d) {
            float lv = glv[gi * DDIM + d];
            float t  = xs[d] - gm[gi * DDIM + d];
            acc += lv + t * t * expf(-lv);
        }
        float lp = glw[gi] - 0.5f * acc;
        if (lp > best) { best = lp; gb = gi; }
    }
    float bestp = -3e38f; int kb = 0;
    for (int kk = 0; kk < KPHI; ++kk) {
        int base = (gb * KPHI + kk) * DDIM;
        float acc = 0.f;
#pragma unroll
        for (int d = 0; d < DDIM; ++d) {
            float lv = plv[base + d];
            float t  = xs[d] - pm[base + d];
            acc += lv + t * t * expf(-lv);
        }
        float lp = plw[gb * KPHI + kk] - 0.5f * acc;
        if (lp > bestp) { bestp = lp; kb = kk; }
    }
    int e = gb * KPHI + kb;
    g_route_e[n] = e;
    g_route_g[n] = gb;
    if (nmask[e] != 0) g_used[e] = 1;
    g_used[NEXP + gb] = 1;
}

// ---------------- kernel 2: build K, blocked Cholesky, Dinv, w-solve, export ----------------
// R14 exactly: SYRK inner dot uses packed fma.rn.f32x2; diag uses sqrtf.
// smem (floats): sA[PACK] | sXp[256*8] | sPan[256*8] | sW[256] | sDinv[8192]
#define SMEM_FLOATS (PACK + TN*8 + TN*8 + TN + 8192)

__global__ void __launch_bounds__(512, 1) k_factor(
    const float* __restrict__ X_exp,  const float* __restrict__ Y_exp,
    const float* __restrict__ X_base, const float* __restrict__ Y_base,
    const float* __restrict__ lls_e, const float* __restrict__ los_e, const float* __restrict__ lno_e,
    const float* __restrict__ lls_b, const float* __restrict__ los_b, const float* __restrict__ lno_b)
{
    int b = blockIdx.x;
    if (!g_used[b]) return;

    extern __shared__ float sm[];
    float* sA    = sm;
    float* sXp   = sA + PACK;
    float* sPan  = sXp + TN * 8;
    float* sW    = sPan + TN * 8;
    float* sDinv = sW + TN;

    int tid  = threadIdx.x;
    int wid  = tid >> 5;
    int lane = tid & 31;

    const float* Xs; const float* Ys; float lls, los, lno;
    if (b < NEXP) {
        Xs = X_exp + (size_t)b * TN * DDIM;  Ys = Y_exp + b * TN;
        lls = lls_e[b]; los = los_e[b]; lno = lno_e[b];
    } else {
        int gb = b - NEXP;
        Xs = X_base + (size_t)gb * TN * DDIM; Ys = Y_base + gb * TN;
        lls = lls_b[gb]; los = los_b[gb]; lno = lno_b[gb];
    }
    float ls2 = expf(2.f * lls);
    float osv = expf(los);
    float nv  = expf(lno) + JIT;
    float c0  = -0.5f / ls2;

    if (tid < TN) {
        int i = tid;
        float v[8];
#pragma unroll
        for (int d = 0; d < DDIM; ++d) v[d] = Xs[i * DDIM + d];
        v[6] = 0.f; v[7] = 0.f;
        float4* dst = (float4*)&sXp[i * 8];
        dst[0] = make_float4(v[0], v[1], v[2], v[3]);
        dst[1] = make_float4(v[4], v[5], v[6], v[7]);
        sW[i] = Ys[i];
    }
    __syncthreads();

    // ---- build K ----
    {
        int row  = tid & 255;
        int half = tid >> 8;
        const float4* X4 = (const float4*)sXp;
        float4 xi0 = X4[row * 2], xi1 = X4[row * 2 + 1];
        int jmid = (row + 1) >> 1;
        int jlo = half ? jmid : 0;
        int jhi = half ? (row + 1) : jmid;
        int idx = cpidx(jlo) + row - jlo;
        for (int j = jlo; j < jhi; ++j) {
            float4 xj0 = X4[j * 2], xj1 = X4[j * 2 + 1];
            float t0 = xi0.x - xj0.x, t1 = xi0.y - xj0.y, t2 = xi0.z - xj0.z, t3 = xi0.w - xj0.w;
            float t4 = xi1.x - xj1.x, t5 = xi1.y - xj1.y;
            float d2 = t0*t0 + t1*t1 + t2*t2 + t3*t3 + t4*t4 + t5*t5;
            float kv = (j == row) ? (osv + nv) : (osv * __expf(c0 * d2));
            sA[idx] = kv;
            idx += 255 - j;
        }
    }
    __syncthreads();

    const float4* pan4 = (const float4*)sPan;

    // ---- blocked Cholesky, panel width 8 ----
    for (int q = 0; q < 32; ++q) {
        int j0   = q * 8;
        int base = j0 + 8;
        int R    = TN - base;

        if (tid < TN) {
            float Ld[8][8];
            float dinv[8];
#pragma unroll
            for (int c = 0; c < 8; ++c) {
                int bidx = cpidx(j0 + c);
#pragma unroll
                for (int r = 0; r < 8; ++r)
                    if (r >= c) Ld[r][c] = sA[bidx + (r - c)];
            }
#pragma unroll
            for (int c = 0; c < 8; ++c) {
                float dsq = Ld[c][c];
#pragma unroll
                for (int p = 0; p < 8; ++p) if (p < c) dsq -= Ld[c][p] * Ld[c][p];
                float dl = sqrtf(dsq);
                Ld[c][c] = dl;
                float inv = 1.0f / dl;
                dinv[c] = inv;
#pragma unroll
                for (int r = 0; r < 8; ++r) {
                    if (r > c) {
                        float v = Ld[r][c];
#pragma unroll
                        for (int p = 0; p < 8; ++p) if (p < c) v -= Ld[r][p] * Ld[c][p];
                        Ld[r][c] = v * inv;
                    }
                }
            }
            if (tid < R) {
                int i = base + tid;
                float a[8];
#pragma unroll
                for (int c = 0; c < 8; ++c) a[c] = sA[cpidx(j0 + c) + (i - (j0 + c))];
#pragma unroll
                for (int c = 0; c < 8; ++c) {
                    float v = a[c];
#pragma unroll
                    for (int p = 0; p < 8; ++p) if (p < c) v -= a[p] * Ld[c][p];
                    a[c] = v * dinv[c];
                }
#pragma unroll
                for (int c = 0; c < 8; ++c) sA[cpidx(j0 + c) + (i - (j0 + c))] = a[c];
                float4* sp = (float4*)&sPan[tid * 8];
                sp[0] = make_float4(a[0], a[1], a[2], a[3]);
                sp[1] = make_float4(a[4], a[5], a[6], a[7]);
            }
#pragma unroll
            for (int r = 0; r < 8; ++r) {
                if (tid == r) {
#pragma unroll
                    for (int c = 0; c < 8; ++c)
                        if (c <= r) sA[cpidx(j0 + c) + (r - c)] = Ld[r][c];
                }
            }
        }
        __syncthreads();

        // ---- SYRK: warp per 8-row tile; packed f32x2 FMA inner dot ----
        if (R > 0) {
            int nt = (R + 7) >> 3;
            for (int rt = wid; rt < nt; rt += 16) {
                int r0 = rt << 3;
                unsigned long long pn[8][4];   // negated packed panel rows
#pragma unroll
                for (int rr = 0; rr < 8; ++rr) {
                    if (r0 + rr < R) {
                        float4 pi0 = pan4[(r0 + rr) * 2];
                        float4 pi1 = pan4[(r0 + rr) * 2 + 1];
                        pn[rr][0] = pk2(-pi0.x, -pi0.y);
                        pn[rr][1] = pk2(-pi0.z, -pi0.w);
                        pn[rr][2] = pk2(-pi1.x, -pi1.y);
                        pn[rr][3] = pk2(-pi1.z, -pi1.w);
                    } else {
                        pn[rr][0] = 0ull; pn[rr][1] = 0ull;
                        pn[rr][2] = 0ull; pn[rr][3] = 0ull;
                    }
                }
                int rmax = min(r0 + 7, R - 1);
                for (int kb = 0; kb <= rmax; kb += 32) {
                    int kk = kb + lane;
                    float4 q0 = make_float4(0.f, 0.f, 0.f, 0.f);
                    float4 q1 = q0;
                    if (kk <= rmax) {
                        q0 = pan4[kk * 2];
                        q1 = pan4[kk * 2 + 1];
                    }
                    unsigned long long qp0 = pk2(q0.x, q0.y);
                    unsigned long long qp1 = pk2(q0.z, q0.w);
                    unsigned long long qp2 = pk2(q1.x, q1.y);
                    unsigned long long qp3 = pk2(q1.z, q1.w);
                    int c = base + kk;
                    int cbase = c * TN - ((c * (c - 1)) >> 1);
#pragma unroll
                    for (int rr = 0; rr < 8; ++rr) {
                        int rho = r0 + rr;
                        if (kk <= rho && rho < R) {
                            int idx = cbase + (rho - kk);
                            float v = sA[idx];
                            unsigned long long t = fma2(pn[rr][0], qp0, pk2(v, 0.f));
                            t = fma2(pn[rr][1], qp1, t);
                            t = fma2(pn[rr][2], qp2, t);
                            t = fma2(pn[rr][3], qp3, t);
                            float2 s = upk2(t);
                            sA[idx] = s.x + s.y;
                        }
                    }
                }
            }
        }
        __syncthreads();
    }

    if (tid < TN) sXp[tid] = 1.0f / sA[cpidx(tid)];
    __syncthreads();

    // ---- epilogue phase 1: warps 1-8 Dinv (smem + global) | warps 9-15 export L ----
    if (wid >= 1 && wid <= 8) {
        int t = wid - 1;
        int s = lane;
        int c0t = 32 * t;
        float x[32];
#pragma unroll
        for (int r = 0; r < 32; ++r) {
            float sum = 0.f;
#pragma unroll
            for (int k = 0; k < 32; ++k) {
                if (k < r) sum += sA[cpidx(c0t + k) + (r - k)] * x[k];
            }
            float ivr = sXp[c0t + r];
            x[r] = (r == s) ? ivr : -sum * ivr;
        }
        float* dsts = sDinv + t * 1024 + s * 32;
        float* dstg = g_dinv + (size_t)b * 8192 + t * 1024 + s * 32;
#pragma unroll
        for (int r = 0; r < 32; ++r) { dsts[r] = x[r]; dstg[r] = x[r]; }
    } else if (wid >= 9) {
        const float4* s4 = (const float4*)sA;
        float4* d4 = (float4*)(g_L + (size_t)b * PACK);
        for (int i = tid - 288; i < PACK / 4; i += 224) d4[i] = s4[i];
    }
    __syncthreads();

    // ---- epilogue phase 2: parallel 8-step w-solve (threads 0-255, row-per-thread) ----
    {
        int r  = tid & 255;
        int hw = r >> 5;
        float acc = (tid < 256) ? sW[r] : 0.f;
#pragma unroll
        for (int T = 0; T < 8; ++T) {
            if (tid < 256 && hw == T) {
                const float* Dt = sDinv + T * 1024;
                float v0 = 0.f, v1 = 0.f, v2 = 0.f, v3 = 0.f;
#pragma unroll
                for (int s = 0; s < 32; s += 4) {
                    float d0 = Dt[(s+0) * 32 + lane];
                    float d1 = Dt[(s+1) * 32 + lane];
                    float d2 = Dt[(s+2) * 32 + lane];
                    float d3 = Dt[(s+3) * 32 + lane];
                    float b0 = __shfl_sync(0xffffffffu, acc, s+0);
                    float b1 = __shfl_sync(0xffffffffu, acc, s+1);
                    float b2 = __shfl_sync(0xffffffffu, acc, s+2);
                    float b3 = __shfl_sync(0xffffffffu, acc, s+3);
                    v0 += d0 * b0; v1 += d1 * b1; v2 += d2 * b2; v3 += d3 * b3;
                }
                sW[r] = (v0 + v1) + (v2 + v3);
            }
            __syncthreads();
            if (tid < 256 && T < 7 && hw > T) {
                int c0i = 32 * T;
                int idx = cpidx(c0i) + (r - c0i);
                float a0 = 0.f, a1 = 0.f, a2 = 0.f, a3 = 0.f;
#pragma unroll
                for (int j = 0; j < 8; ++j) {
                    int c = c0i + j * 4;
                    float z0 = sW[c], z1 = sW[c+1], z2 = sW[c+2], z3 = sW[c+3];
                    float l0 = sA[idx]; idx += 255 - c;
                    float l1 = sA[idx]; idx += 254 - c;
                    float l2 = sA[idx]; idx += 253 - c;
                    float l3 = sA[idx]; idx += 252 - c;
                    a0 += l0 * z0; a1 += l1 * z1; a2 += l2 * z2; a3 += l3 * z3;
                }
                acc -= (a0 + a1) + (a2 + a3);
            }
        }
        if (tid < 256) g_w[b * TN + r] = sW[r];
    }
}

// ---------------- kernel 3: prediction, block-per-task, row-per-thread ----------------
__global__ void __launch_bounds__(256) k_predict(
    const float* __restrict__ Xt,
    const float* __restrict__ X_exp, const float* __restrict__ X_base,
    const float* __restrict__ lls_e, const float* __restrict__ los_e, const float* __restrict__ lno_e,
    const float* __restrict__ lls_b, const float* __restrict__ los_b, const float* __restrict__ lno_b,
    const int*   __restrict__ nmask)
{
    __shared__ float sDv[8192];
    __shared__ float sZ[TN];
    __shared__ float sRed[16];

    int task = blockIdx.x;            // 0..2047
    int n = task >> 1;
    bool is_base = (task & 1);

    int p; const float* Xtr; float lls, los, lno;
    if (!is_base) {
        int e = g_route_e[n];
        if (nmask[e] == 0) return;    // uniform across block
        p = e; Xtr = X_exp + (size_t)e * TN * DDIM;
        lls = lls_e[e]; los = los_e[e]; lno = lno_e[e];
    } else {
        int g = g_route_g[n];
        p = NEXP + g; Xtr = X_base + (size_t)g * TN * DDIM;
        lls = lls_b[g]; los = los_b[g]; lno = lno_b[g];
    }
    float ls2 = expf(2.f * lls);
    float osv = expf(los);
    float nv  = expf(lno) + JIT;
    float c0  = -0.5f / ls2;

    int r    = threadIdx.x;           // row 0..255
    int wid  = r >> 5;
    int lane = r & 31;

    // stage Dinv into smem (coalesced float4)
    {
        const float4* dv4 = (const float4*)(g_dinv + (size_t)p * 8192);
        float4* dd4 = (float4*)sDv;
#pragma unroll
        for (int i = 0; i < 8; ++i) dd4[r + i * 256] = dv4[r + i * 256];
    }

    // k*(x_n, Xtr[r]) -> initial residual acc
    float acc;
    {
        float d2 = 0.f;
#pragma unroll
        for (int d = 0; d < DDIM; ++d) {
            float tv = Xt[n * DDIM + d] - Xtr[r * DDIM + d];
            d2 += tv * tv;
        }
        acc = osv * __expf(c0 * d2);
    }
    float wr = g_w[p * TN + r];
    const float* Lp = g_L + (size_t)p * PACK;
    __syncthreads();   // sDv ready

    // right-looking block forward solve: 8 steps
#pragma unroll
    for (int T = 0; T < 8; ++T) {
        int c0i = 32 * T;
        int idx0 = c0i * TN - ((c0i * (c0i - 1)) >> 1) + (r - c0i);
        float lv[16];
        // prefetch first 16 L values BEFORE the barrier (addresses data-independent)
        if (T < 7 && wid > T) {
            int idx = idx0;
#pragma unroll
            for (int k = 0; k < 16; ++k) { lv[k] = Lp[idx]; idx += 255 - (c0i + k); }
        }
        if (wid == T) {
            // z_tile = Dinv_T * acc_tile (smem Dinv, shfl broadcast)
            const float* Dt = sDv + T * 1024;
            float v0 = 0.f, v1 = 0.f, v2 = 0.f, v3 = 0.f;
#pragma unroll
            for (int s = 0; s < 32; s += 4) {
                float d0 = Dt[(s+0) * 32 + lane];
                float d1 = Dt[(s+1) * 32 + lane];
                float d2 = Dt[(s+2) * 32 + lane];
                float d3 = Dt[(s+3) * 32 + lane];
                float b0 = __shfl_sync(0xffffffffu, acc, s+0);
                float b1 = __shfl_sync(0xffffffffu, acc, s+1);
                float b2 = __shfl_sync(0xffffffffu, acc, s+2);
                float b3 = __shfl_sync(0xffffffffu, acc, s+3);
                v0 += d0 * b0; v1 += d1 * b1; v2 += d2 * b2; v3 += d3 * b3;
            }
            sZ[r] = (v0 + v1) + (v2 + v3);
        }
        __syncthreads();
        if (T < 7 && wid > T) {
            float a0 = 0.f, a1 = 0.f, a2 = 0.f, a3 = 0.f;
            // first 16 from prefetched registers
#pragma unroll
            for (int k = 0; k < 16; k += 4) {
                a0 += lv[k+0] * sZ[c0i+k+0];
                a1 += lv[k+1] * sZ[c0i+k+1];
                a2 += lv[k+2] * sZ[c0i+k+2];
                a3 += lv[k+3] * sZ[c0i+k+3];
            }
            // remaining 16 streamed (independent loads)
            int idx = idx0 + 16 * 255 - 16 * c0i - 120;
#pragma unroll
            for (int j = 4; j < 8; ++j) {
                int c = c0i + j * 4;
                float z0 = sZ[c], z1 = sZ[c+1], z2 = sZ[c+2], z3 = sZ[c+3];
                float l0 = Lp[idx]; idx += 255 - c;
                float l1 = Lp[idx]; idx += 254 - c;
                float l2 = Lp[idx]; idx += 253 - c;
                float l3 = Lp[idx]; idx += 252 - c;
                a0 += l0 * z0; a1 += l1 * z1; a2 += l2 * z2; a3 += l3 * z3;
            }
            acc -= (a0 + a1) + (a2 + a3);
        }
    }

    // reduce qq = |z|^2, mu = z.w
    float z = sZ[r];
    float qq = z * z;
    float mu = z * wr;
#pragma unroll
    for (int o = 16; o; o >>= 1) {
        qq += __shfl_xor_sync(0xffffffffu, qq, o);
        mu += __shfl_xor_sync(0xffffffffu, mu, o);
    }
    if (lane == 0) { sRed[wid] = qq; sRed[8 + wid] = mu; }
    __syncthreads();
    if (r == 0) {
        float tq = 0.f, tm = 0.f;
#pragma unroll
        for (int i = 0; i < 8; ++i) { tq += sRed[i]; tm += sRed[8 + i]; }
        float var = fmaxf(osv - tq, JIT) + nv;
        float prior = osv + nv;
        if (!is_base) { g_mu_e[n] = tm; g_var_e[n] = var; g_prior_e[n] = prior; }
        else          { g_mu_b[n] = tm; g_var_b[n] = var; g_prior_b[n] = prior; }
    }
}

// ---------------- kernel 4: rBCM combine ----------------
__global__ void k_combine(const int* __restrict__ nmask, float* __restrict__ out)
{
    int n = blockIdx.x * blockDim.x + threadIdx.x;
    if (n >= NTEST) return;
    int e = g_route_e[n];
    bool isnull = (nmask[e] == 0);
    float mub = g_mu_b[n], varb = g_var_b[n], prb = g_prior_b[n];
    float bb = fmaxf(0.5f * (logf(prb) - logf(varb)), 0.f);
    float be = 0.f, te = 0.f, me = 0.f;
    if (!isnull) {
        float mue = g_mu_e[n], vare = g_var_e[n], pre = g_prior_e[n];
        be = fmaxf(0.5f * (logf(pre) - logf(vare)), 0.f);
        te = be / vare;
        me = be * mue / vare;
    }
    float prec = te + bb / varb + (1.f - be - bb) / prb;
    prec = fmaxf(prec, 1e-6f);
    float mean = (me + bb * mub / varb) / prec;
    out[n] = mean;
    out[NTEST + n] = 1.f / prec;
}

// ---------------- launch ----------------
extern "C" void kernel_launch(void* const* d_in, const int* in_sizes, int n_in,
                              void* d_out, int out_size)
{
    const float* X_test   = (const float*)d_in[0];
    const float* X_exp    = (const float*)d_in[1];
    const float* Y_exp    = (const float*)d_in[2];
    const float* X_base   = (const float*)d_in[3];
    const float* Y_base   = (const float*)d_in[4];
    const float* lls_e    = (const float*)d_in[5];
    const float* los_e    = (const float*)d_in[6];
    const float* lno_e    = (const float*)d_in[7];
    const float* lls_b    = (const float*)d_in[8];
    const float* los_b    = (const float*)d_in[9];
    const float* lno_b    = (const float*)d_in[10];
    const float* smean    = (const float*)d_in[11];
    const float* sscale   = (const float*)d_in[12];
    const float* gm       = (const float*)d_in[13];
    const float* glv      = (const float*)d_in[14];
    const float* glw      = (const float*)d_in[15];
    const float* pm       = (const float*)d_in[16];
    const float* plv      = (const float*)d_in[17];
    const float* plw      = (const float*)d_in[18];
    const int*   nmask    = (const int*)d_in[19];
    float* out = (float*)d_out;

    static_assert(SMEM_FLOATS * 4 <= 232448, "smem factor");
    cudaFuncSetAttribute(k_factor, cudaFuncAttributeMaxDynamicSharedMemorySize,
                         SMEM_FLOATS * 4);

    k_zero<<<(NPROB + 255) / 256, 256>>>();
    k_route<<<(NTEST + 255) / 256, 256>>>(X_test, smean, sscale, gm, glv, glw,
                                          pm, plv, plw, nmask);
    k_factor<<<NPROB, 512, SMEM_FLOATS * 4>>>(X_exp, Y_exp, X_base, Y_base,
                                              lls_e, los_e, lno_e,
                                              lls_b, los_b, lno_b);
    k_predict<<<2 * NTEST, 256>>>(X_test, X_exp, X_base,
                                  lls_e, los_e, lno_e,
                                  lls_b, los_b, lno_b, nmask);
    k_combine<<<(NTEST + 255) / 256, 256>>>(nmask, out);
}

// round 17
// speedup vs baseline: 1.5670x; 1.0842x over previous
#include <cuda_runtime.h>
#include <cuda_bf16.h>
#include <math.h>

#define TN     256
#define DDIM   6
#define NEXP   540
#define NGEO   20
#define KPHI   27
#define NPROB  560          // 540 experts + 20 baselines
#define NTEST  1024
#define PACK   32896        // 256*257/2
#define JIT    1e-4f

// ---------------- packed f32x2 helpers (sm_103a FFMA2) ----------------
__device__ __forceinline__ unsigned long long pk2(float lo, float hi) {
    unsigned long long r;
    asm("mov.b64 %0, {%1, %2};" : "=l"(r) : "f"(lo), "f"(hi));
    return r;
}
__device__ __forceinline__ unsigned long long fma2(unsigned long long a,
                                                   unsigned long long b,
                                                   unsigned long long c) {
    unsigned long long r;
    asm("fma.rn.f32x2 %0, %1, %2, %3;" : "=l"(r) : "l"(a), "l"(b), "l"(c));
    return r;
}
__device__ __forceinline__ float2 upk2(unsigned long long a) {
    float lo, hi;
    asm("mov.b64 {%0, %1}, %2;" : "=f"(lo), "=f"(hi) : "l"(a));
    return make_float2(lo, hi);
}

// ---------------- static device scratch ----------------
__device__ float g_L[(size_t)NPROB * PACK];           // packed column-major lower L
__device__ float g_w[NPROB * TN];                     // w = L^-1 y
__device__ float g_dinv[(size_t)NPROB * 8 * 32 * 32]; // 32x32 diag-block inverses [tile][s][r]
__device__ int   g_used[NPROB];
__device__ int   g_route_e[NTEST];
__device__ int   g_route_g[NTEST];
__device__ float g_mu_e[NTEST],  g_var_e[NTEST],  g_prior_e[NTEST];
__device__ float g_mu_b[NTEST],  g_var_b[NTEST],  g_prior_b[NTEST];

__device__ __forceinline__ int cpidx(int j) { return j * TN - ((j * (j - 1)) >> 1); }

// ---------------- kernel 0: clear used flags ----------------
__global__ void k_zero() {
    int i = blockIdx.x * blockDim.x + threadIdx.x;
    if (i < NPROB) g_used[i] = 0;
}

// ---------------- kernel 1: 2-level GMM routing ----------------
__global__ void k_route(const float* __restrict__ Xt,
                        const float* __restrict__ smean, const float* __restrict__ sscale,
                        const float* __restrict__ gm,    const float* __restrict__ glv,
                        const float* __restrict__ glw,
                        const float* __restrict__ pm,    const float* __restrict__ plv,
                        const float* __restrict__ plw,
                        const int*   __restrict__ nmask)
{
    int n = blockIdx.x * blockDim.x + threadIdx.x;
    if (n >= NTEST) return;
    float xs[DDIM];
#pragma unroll
    for (int d = 0; d < DDIM; ++d) xs[d] = (Xt[n * DDIM + d] - smean[d]) / sscale[d];

    float best = -3e38f; int gb = 0;
    for (int gi = 0; gi < NGEO; ++gi) {
        float acc = 0.f;
#pragma unroll
        for (int d = 0; d < DDIM; ++d) {
            float lv = glv[gi * DDIM + d];
            float t  = xs[d] - gm[gi * DDIM + d];
            acc += lv + t * t * expf(-lv);
        }
        float lp = glw[gi] - 0.5f * acc;
        if (lp > best) { best = lp; gb = gi; }
    }
    float bestp = -3e38f; int kb = 0;
    for (int kk = 0; kk < KPHI; ++kk) {
        int base = (gb * KPHI + kk) * DDIM;
        float acc = 0.f;
#pragma unroll
        for (int d = 0; d < DDIM; ++d) {
            float lv = plv[base + d];
            float t  = xs[d] - pm[base + d];
            acc += lv + t * t * expf(-lv);
        }
        float lp = plw[gb * KPHI + kk] - 0.5f * acc;
        if (lp > bestp) { bestp = lp; kb = kk; }
    }
    int e = gb * KPHI + kb;
    g_route_e[n] = e;
    g_route_g[n] = gb;
    if (nmask[e] != 0) g_used[e] = 1;
    g_used[NEXP + gb] = 1;
}

// ---------------- kernel 2: build K, blocked Cholesky, Dinv, w-solve, export ----------------
// R14/R16 exactly (proven 193.3 us config) — DO NOT TOUCH.
// smem (floats): sA[PACK] | sXp[256*8] | sPan[256*8] | sW[256] | sDinv[8192]
#define SMEM_FLOATS (PACK + TN*8 + TN*8 + TN + 8192)

__global__ void __launch_bounds__(512, 1) k_factor(
    const float* __restrict__ X_exp,  const float* __restrict__ Y_exp,
    const float* __restrict__ X_base, const float* __restrict__ Y_base,
    const float* __restrict__ lls_e, const float* __restrict__ los_e, const float* __restrict__ lno_e,
    const float* __restrict__ lls_b, const float* __restrict__ los_b, const float* __restrict__ lno_b)
{
    int b = blockIdx.x;
    if (!g_used[b]) return;

    extern __shared__ float sm[];
    float* sA    = sm;
    float* sXp   = sA + PACK;
    float* sPan  = sXp + TN * 8;
    float* sW    = sPan + TN * 8;
    float* sDinv = sW + TN;

    int tid  = threadIdx.x;
    int wid  = tid >> 5;
    int lane = tid & 31;

    const float* Xs; const float* Ys; float lls, los, lno;
    if (b < NEXP) {
        Xs = X_exp + (size_t)b * TN * DDIM;  Ys = Y_exp + b * TN;
        lls = lls_e[b]; los = los_e[b]; lno = lno_e[b];
    } else {
        int gb = b - NEXP;
        Xs = X_base + (size_t)gb * TN * DDIM; Ys = Y_base + gb * TN;
        lls = lls_b[gb]; los = los_b[gb]; lno = lno_b[gb];
    }
    float ls2 = expf(2.f * lls);
    float osv = expf(los);
    float nv  = expf(lno) + JIT;
    float c0  = -0.5f / ls2;

    if (tid < TN) {
        int i = tid;
        float v[8];
#pragma unroll
        for (int d = 0; d < DDIM; ++d) v[d] = Xs[i * DDIM + d];
        v[6] = 0.f; v[7] = 0.f;
        float4* dst = (float4*)&sXp[i * 8];
        dst[0] = make_float4(v[0], v[1], v[2], v[3]);
        dst[1] = make_float4(v[4], v[5], v[6], v[7]);
        sW[i] = Ys[i];
    }
    __syncthreads();

    // ---- build K ----
    {
        int row  = tid & 255;
        int half = tid >> 8;
        const float4* X4 = (const float4*)sXp;
        float4 xi0 = X4[row * 2], xi1 = X4[row * 2 + 1];
        int jmid = (row + 1) >> 1;
        int jlo = half ? jmid : 0;
        int jhi = half ? (row + 1) : jmid;
        int idx = cpidx(jlo) + row - jlo;
        for (int j = jlo; j < jhi; ++j) {
            float4 xj0 = X4[j * 2], xj1 = X4[j * 2 + 1];
            float t0 = xi0.x - xj0.x, t1 = xi0.y - xj0.y, t2 = xi0.z - xj0.z, t3 = xi0.w - xj0.w;
            float t4 = xi1.x - xj1.x, t5 = xi1.y - xj1.y;
            float d2 = t0*t0 + t1*t1 + t2*t2 + t3*t3 + t4*t4 + t5*t5;
            float kv = (j == row) ? (osv + nv) : (osv * __expf(c0 * d2));
            sA[idx] = kv;
            idx += 255 - j;
        }
    }
    __syncthreads();

    const float4* pan4 = (const float4*)sPan;

    // ---- blocked Cholesky, panel width 8 ----
    for (int q = 0; q < 32; ++q) {
        int j0   = q * 8;
        int base = j0 + 8;
        int R    = TN - base;

        if (tid < TN) {
            float Ld[8][8];
            float dinv[8];
#pragma unroll
            for (int c = 0; c < 8; ++c) {
                int bidx = cpidx(j0 + c);
#pragma unroll
                for (int r = 0; r < 8; ++r)
                    if (r >= c) Ld[r][c] = sA[bidx + (r - c)];
            }
#pragma unroll
            for (int c = 0; c < 8; ++c) {
                float dsq = Ld[c][c];
#pragma unroll
                for (int p = 0; p < 8; ++p) if (p < c) dsq -= Ld[c][p] * Ld[c][p];
                float dl = sqrtf(dsq);
                Ld[c][c] = dl;
                float inv = 1.0f / dl;
                dinv[c] = inv;
#pragma unroll
                for (int r = 0; r < 8; ++r) {
                    if (r > c) {
                        float v = Ld[r][c];
#pragma unroll
                        for (int p = 0; p < 8; ++p) if (p < c) v -= Ld[r][p] * Ld[c][p];
                        Ld[r][c] = v * inv;
                    }
                }
            }
            if (tid < R) {
                int i = base + tid;
                float a[8];
#pragma unroll
                for (int c = 0; c < 8; ++c) a[c] = sA[cpidx(j0 + c) + (i - (j0 + c))];
#pragma unroll
                for (int c = 0; c < 8; ++c) {
                    float v = a[c];
#pragma unroll
                    for (int p = 0; p < 8; ++p) if (p < c) v -= a[p] * Ld[c][p];
                    a[c] = v * dinv[c];
                }
#pragma unroll
                for (int c = 0; c < 8; ++c) sA[cpidx(j0 + c) + (i - (j0 + c))] = a[c];
                float4* sp = (float4*)&sPan[tid * 8];
                sp[0] = make_float4(a[0], a[1], a[2], a[3]);
                sp[1] = make_float4(a[4], a[5], a[6], a[7]);
            }
#pragma unroll
            for (int r = 0; r < 8; ++r) {
                if (tid == r) {
#pragma unroll
                    for (int c = 0; c < 8; ++c)
                        if (c <= r) sA[cpidx(j0 + c) + (r - c)] = Ld[r][c];
                }
            }
        }
        __syncthreads();

        // ---- SYRK: warp per 8-row tile; packed f32x2 FMA inner dot ----
        if (R > 0) {
            int nt = (R + 7) >> 3;
            for (int rt = wid; rt < nt; rt += 16) {
                int r0 = rt << 3;
                unsigned long long pn[8][4];   // negated packed panel rows
#pragma unroll
                for (int rr = 0; rr < 8; ++rr) {
                    if (r0 + rr < R) {
                        float4 pi0 = pan4[(r0 + rr) * 2];
                        float4 pi1 = pan4[(r0 + rr) * 2 + 1];
                        pn[rr][0] = pk2(-pi0.x, -pi0.y);
                        pn[rr][1] = pk2(-pi0.z, -pi0.w);
                        pn[rr][2] = pk2(-pi1.x, -pi1.y);
                        pn[rr][3] = pk2(-pi1.z, -pi1.w);
                    } else {
                        pn[rr][0] = 0ull; pn[rr][1] = 0ull;
                        pn[rr][2] = 0ull; pn[rr][3] = 0ull;
                    }
                }
                int rmax = min(r0 + 7, R - 1);
                for (int kb = 0; kb <= rmax; kb += 32) {
                    int kk = kb + lane;
                    float4 q0 = make_float4(0.f, 0.f, 0.f, 0.f);
                    float4 q1 = q0;
                    if (kk <= rmax) {
                        q0 = pan4[kk * 2];
                        q1 = pan4[kk * 2 + 1];
                    }
                    unsigned long long qp0 = pk2(q0.x, q0.y);
                    unsigned long long qp1 = pk2(q0.z, q0.w);
                    unsigned long long qp2 = pk2(q1.x, q1.y);
                    unsigned long long qp3 = pk2(q1.z, q1.w);
                    int c = base + kk;
                    int cbase = c * TN - ((c * (c - 1)) >> 1);
#pragma unroll
                    for (int rr = 0; rr < 8; ++rr) {
                        int rho = r0 + rr;
                        if (kk <= rho && rho < R) {
                            int idx = cbase + (rho - kk);
                            float v = sA[idx];
                            unsigned long long t = fma2(pn[rr][0], qp0, pk2(v, 0.f));
                            t = fma2(pn[rr][1], qp1, t);
                            t = fma2(pn[rr][2], qp2, t);
                            t = fma2(pn[rr][3], qp3, t);
                            float2 s = upk2(t);
                            sA[idx] = s.x + s.y;
                        }
                    }
                }
            }
        }
        __syncthreads();
    }

    if (tid < TN) sXp[tid] = 1.0f / sA[cpidx(tid)];
    __syncthreads();

    // ---- epilogue phase 1: warps 1-8 Dinv (smem + global) | warps 9-15 export L ----
    if (wid >= 1 && wid <= 8) {
        int t = wid - 1;
        int s = lane;
        int c0t = 32 * t;
        float x[32];
#pragma unroll
        for (int r = 0; r < 32; ++r) {
            float sum = 0.f;
#pragma unroll
            for (int k = 0; k < 32; ++k) {
                if (k < r) sum += sA[cpidx(c0t + k) + (r - k)] * x[k];
            }
            float ivr = sXp[c0t + r];
            x[r] = (r == s) ? ivr : -sum * ivr;
        }
        float* dsts = sDinv + t * 1024 + s * 32;
        float* dstg = g_dinv + (size_t)b * 8192 + t * 1024 + s * 32;
#pragma unroll
        for (int r = 0; r < 32; ++r) { dsts[r] = x[r]; dstg[r] = x[r]; }
    } else if (wid >= 9) {
        const float4* s4 = (const float4*)sA;
        float4* d4 = (float4*)(g_L + (size_t)b * PACK);
        for (int i = tid - 288; i < PACK / 4; i += 224) d4[i] = s4[i];
    }
    __syncthreads();

    // ---- epilogue phase 2: parallel 8-step w-solve (threads 0-255, row-per-thread) ----
    {
        int r  = tid & 255;
        int hw = r >> 5;
        float acc = (tid < 256) ? sW[r] : 0.f;
#pragma unroll
        for (int T = 0; T < 8; ++T) {
            if (tid < 256 && hw == T) {
                const float* Dt = sDinv + T * 1024;
                float v0 = 0.f, v1 = 0.f, v2 = 0.f, v3 = 0.f;
#pragma unroll
                for (int s = 0; s < 32; s += 4) {
                    float d0 = Dt[(s+0) * 32 + lane];
                    float d1 = Dt[(s+1) * 32 + lane];
                    float d2 = Dt[(s+2) * 32 + lane];
                    float d3 = Dt[(s+3) * 32 + lane];
                    float b0 = __shfl_sync(0xffffffffu, acc, s+0);
                    float b1 = __shfl_sync(0xffffffffu, acc, s+1);
                    float b2 = __shfl_sync(0xffffffffu, acc, s+2);
                    float b3 = __shfl_sync(0xffffffffu, acc, s+3);
                    v0 += d0 * b0; v1 += d1 * b1; v2 += d2 * b2; v3 += d3 * b3;
                }
                sW[r] = (v0 + v1) + (v2 + v3);
            }
            __syncthreads();
            if (tid < 256 && T < 7 && hw > T) {
                int c0i = 32 * T;
                int idx = cpidx(c0i) + (r - c0i);
                float a0 = 0.f, a1 = 0.f, a2 = 0.f, a3 = 0.f;
#pragma unroll
                for (int j = 0; j < 8; ++j) {
                    int c = c0i + j * 4;
                    float z0 = sW[c], z1 = sW[c+1], z2 = sW[c+2], z3 = sW[c+3];
                    float l0 = sA[idx]; idx += 255 - c;
                    float l1 = sA[idx]; idx += 254 - c;
                    float l2 = sA[idx]; idx += 253 - c;
                    float l3 = sA[idx]; idx += 252 - c;
                    a0 += l0 * z0; a1 += l1 * z1; a2 += l2 * z2; a3 += l3 * z3;
                }
                acc -= (a0 + a1) + (a2 + a3);
            }
        }
        if (tid < 256) g_w[b * TN + r] = sW[r];
    }
}

// ---------------- kernel 3: prediction, block-per-task, row-per-thread ----------------
// R16 + full 32-deep pre-barrier L prefetch (third application of proven pattern)
__global__ void __launch_bounds__(256) k_predict(
    const float* __restrict__ Xt,
    const float* __restrict__ X_exp, const float* __restrict__ X_base,
    const float* __restrict__ lls_e, const float* __restrict__ los_e, const float* __restrict__ lno_e,
    const float* __restrict__ lls_b, const float* __restrict__ los_b, const float* __restrict__ lno_b,
    const int*   __restrict__ nmask)
{
    __shared__ float sDv[8192];
    __shared__ float sZ[TN];
    __shared__ float sRed[16];

    int task = blockIdx.x;            // 0..2047
    int n = task >> 1;
    bool is_base = (task & 1);

    int p; const float* Xtr; float lls, los, lno;
    if (!is_base) {
        int e = g_route_e[n];
        if (nmask[e] == 0) return;    // uniform across block
        p = e; Xtr = X_exp + (size_t)e * TN * DDIM;
        lls = lls_e[e]; los = los_e[e]; lno = lno_e[e];
    } else {
        int g = g_route_g[n];
        p = NEXP + g; Xtr = X_base + (size_t)g * TN * DDIM;
        lls = lls_b[g]; los = los_b[g]; lno = lno_b[g];
    }
    float ls2 = expf(2.f * lls);
    float osv = expf(los);
    float nv  = expf(lno) + JIT;
    float c0  = -0.5f / ls2;

    int r    = threadIdx.x;           // row 0..255
    int wid  = r >> 5;
    int lane = r & 31;

    // stage Dinv into smem (coalesced float4)
    {
        const float4* dv4 = (const float4*)(g_dinv + (size_t)p * 8192);
        float4* dd4 = (float4*)sDv;
#pragma unroll
        for (int i = 0; i < 8; ++i) dd4[r + i * 256] = dv4[r + i * 256];
    }

    // k*(x_n, Xtr[r]) -> initial residual acc
    float acc;
    {
        float d2 = 0.f;
#pragma unroll
        for (int d = 0; d < DDIM; ++d) {
            float tv = Xt[n * DDIM + d] - Xtr[r * DDIM + d];
            d2 += tv * tv;
        }
        acc = osv * __expf(c0 * d2);
    }
    float wr = g_w[p * TN + r];
    const float* Lp = g_L + (size_t)p * PACK;
    __syncthreads();   // sDv ready

    // right-looking block forward solve: 8 steps
#pragma unroll
    for (int T = 0; T < 8; ++T) {
        int c0i = 32 * T;
        int idx0 = c0i * TN - ((c0i * (c0i - 1)) >> 1) + (r - c0i);
        float lv[32];
        // prefetch ALL 32 L values BEFORE the barrier (addresses data-independent)
        if (T < 7 && wid > T) {
            int idx = idx0;
#pragma unroll
            for (int k = 0; k < 32; ++k) { lv[k] = Lp[idx]; idx += 255 - (c0i + k); }
        }
        if (wid == T) {
            // z_tile = Dinv_T * acc_tile (smem Dinv, shfl broadcast)
            const float* Dt = sDv + T * 1024;
            float v0 = 0.f, v1 = 0.f, v2 = 0.f, v3 = 0.f;
#pragma unroll
            for (int s = 0; s < 32; s += 4) {
                float d0 = Dt[(s+0) * 32 + lane];
                float d1 = Dt[(s+1) * 32 + lane];
                float d2 = Dt[(s+2) * 32 + lane];
                float d3 = Dt[(s+3) * 32 + lane];
                float b0 = __shfl_sync(0xffffffffu, acc, s+0);
                float b1 = __shfl_sync(0xffffffffu, acc, s+1);
                float b2 = __shfl_sync(0xffffffffu, acc, s+2);
                float b3 = __shfl_sync(0xffffffffu, acc, s+3);
                v0 += d0 * b0; v1 += d1 * b1; v2 += d2 * b2; v3 += d3 * b3;
            }
            sZ[r] = (v0 + v1) + (v2 + v3);
        }
        __syncthreads();
        if (T < 7 && wid > T) {
            float a0 = 0.f, a1 = 0.f, a2 = 0.f, a3 = 0.f;
#pragma unroll
            for (int k = 0; k < 32; k += 4) {
                a0 += lv[k+0] * sZ[c0i+k+0];
                a1 += lv[k+1] * sZ[c0i+k+1];
                a2 += lv[k+2] * sZ[c0i+k+2];
                a3 += lv[k+3] * sZ[c0i+k+3];
            }
            acc -= (a0 + a1) + (a2 + a3);
        }
    }

    // reduce qq = |z|^2, mu = z.w
    float z = sZ[r];
    float qq = z * z;
    float mu = z * wr;
#pragma unroll
    for (int o = 16; o; o >>= 1) {
        qq += __shfl_xor_sync(0xffffffffu, qq, o);
        mu += __shfl_xor_sync(0xffffffffu, mu, o);
    }
    if (lane == 0) { sRed[wid] = qq; sRed[8 + wid] = mu; }
    __syncthreads();
    if (r == 0) {
        float tq = 0.f, tm = 0.f;
#pragma unroll
        for (int i = 0; i < 8; ++i) { tq += sRed[i]; tm += sRed[8 + i]; }
        float var = fmaxf(osv - tq, JIT) + nv;
        float prior = osv + nv;
        if (!is_base) { g_mu_e[n] = tm; g_var_e[n] = var; g_prior_e[n] = prior; }
        else          { g_mu_b[n] = tm; g_var_b[n] = var; g_prior_b[n] = prior; }
    }
}

// ---------------- kernel 4: rBCM combine ----------------
__global__ void k_combine(const int* __restrict__ nmask, float* __restrict__ out)
{
    int n = blockIdx.x * blockDim.x + threadIdx.x;
    if (n >= NTEST) return;
    int e = g_route_e[n];
    bool isnull = (nmask[e] == 0);
    float mub = g_mu_b[n], varb = g_var_b[n], prb = g_prior_b[n];
    float bb = fmaxf(0.5f * (logf(prb) - logf(varb)), 0.f);
    float be = 0.f, te = 0.f, me = 0.f;
    if (!isnull) {
        float mue = g_mu_e[n], vare = g_var_e[n], pre = g_prior_e[n];
        be = fmaxf(0.5f * (logf(pre) - logf(vare)), 0.f);
        te = be / vare;
        me = be * mue / vare;
    }
    float prec = te + bb / varb + (1.f - be - bb) / prb;
    prec = fmaxf(prec, 1e-6f);
    float mean = (me + bb * mub / varb) / prec;
    out[n] = mean;
    out[NTEST + n] = 1.f / prec;
}

// ---------------- launch ----------------
extern "C" void kernel_launch(void* const* d_in, const int* in_sizes, int n_in,
                              void* d_out, int out_size)
{
    const float* X_test   = (const float*)d_in[0];
    const float* X_exp    = (const float*)d_in[1];
    const float* Y_exp    = (const float*)d_in[2];
    const float* X_base   = (const float*)d_in[3];
    const float* Y_base   = (const float*)d_in[4];
    const float* lls_e    = (const float*)d_in[5];
    const float* los_e    = (const float*)d_in[6];
    const float* lno_e    = (const float*)d_in[7];
    const float* lls_b    = (const float*)d_in[8];
    const float* los_b    = (const float*)d_in[9];
    const float* lno_b    = (const float*)d_in[10];
    const float* smean    = (const float*)d_in[11];
    const float* sscale   = (const float*)d_in[12];
    const float* gm       = (const float*)d_in[13];
    const float* glv      = (const float*)d_in[14];
    const float* glw      = (const float*)d_in[15];
    const float* pm       = (const float*)d_in[16];
    const float* plv      = (const float*)d_in[17];
    const float* plw      = (const float*)d_in[18];
    const int*   nmask    = (const int*)d_in[19];
    float* out = (float*)d_out;

    static_assert(SMEM_FLOATS * 4 <= 232448, "smem factor");
    cudaFuncSetAttribute(k_factor, cudaFuncAttributeMaxDynamicSharedMemorySize,
                         SMEM_FLOATS * 4);

    k_zero<<<(NPROB + 255) / 256, 256>>>();
    k_route<<<(NTEST + 255) / 256, 256>>>(X_test, smean, sscale, gm, glv, glw,
                                          pm, plv, plw, nmask);
    k_factor<<<NPROB, 512, SMEM_FLOATS * 4>>>(X_exp, Y_exp, X_base, Y_base,
                                              lls_e, los_e, lno_e,
                                              lls_b, los_b, lno_b);
    k_predict<<<2 * NTEST, 256>>>(X_test, X_exp, X_base,
                                  lls_e, los_e, lno_e,
                                  lls_b, los_b, lno_b, nmask);
    k_combine<<<(NTEST + 255) / 256, 256>>>(nmask, out);
}